// round 2
// baseline (speedup 1.0000x reference)
#include <cuda_runtime.h>
#include <math.h>

// ---- static problem dims (from reference) ----
#define NB 2
#define HID 2048
#define NH 16
#define DH 128
#define NL 8
#define NV 32000
#define SEQ 2048
#define OFFR 1024
#define RR 1025
#define PHEAP 11272
#define Q3H 6144
#define FF 8192
#define NKEY 2049      // layer0: S+1 ; layers>=1: R+OFF  (both 2049)
#define SPLITS 8
#define CHUNK 257      // ceil(2049/8)

// ---- scratch (device globals: no allocation allowed) ----
__device__ float g_x[NB * HID];
__device__ float g_xn[NB * HID];
__device__ float g_qkv[NB * Q3H];
__device__ float g_h1[NB * FF];
__device__ float g_part[NB * NH * SPLITS * (DH + 2)];
__device__ float g_logits[NB * NV];

// ---- x + positional encoding (pos = 2048, static) ----
__global__ void pe_add_kernel(const float* __restrict__ xin) {
    int i = blockIdx.x * blockDim.x + threadIdx.x;
    if (i >= NB * HID) return;
    int c = i % HID;
    int half = c >> 1;
    double div = exp(-log(10000.0) * (2.0 * half) / (double)HID);
    double ang = (double)SEQ * div;
    float pe = (c & 1) ? (float)cos(ang) : (float)sin(ang);
    g_x[i] = xin[i] + pe;
}

// ---- LayerNorm: grid=NB, block=512 ----
__global__ void ln_kernel(const float* __restrict__ in, float* __restrict__ out,
                          const float* __restrict__ gg, const float* __restrict__ bb) {
    int b = blockIdx.x;
    int tid = threadIdx.x;
    __shared__ float red[16];
    const float* xb = in + b * HID;
    float vals[4];
    float s = 0.f;
#pragma unroll
    for (int k = 0; k < 4; k++) { vals[k] = xb[tid + k * 512]; s += vals[k]; }
    for (int o = 16; o; o >>= 1) s += __shfl_xor_sync(~0u, s, o);
    if ((tid & 31) == 0) red[tid >> 5] = s;
    __syncthreads();
    if (tid < 32) {
        float v = (tid < 16) ? red[tid] : 0.f;
        for (int o = 8; o; o >>= 1) v += __shfl_xor_sync(~0u, v, o);
        if (tid == 0) red[0] = v;
    }
    __syncthreads();
    float mean = red[0] * (1.f / HID);
    __syncthreads();
    float s2 = 0.f;
#pragma unroll
    for (int k = 0; k < 4; k++) { float d = vals[k] - mean; s2 += d * d; }
    for (int o = 16; o; o >>= 1) s2 += __shfl_xor_sync(~0u, s2, o);
    if ((tid & 31) == 0) red[tid >> 5] = s2;
    __syncthreads();
    if (tid < 32) {
        float v = (tid < 16) ? red[tid] : 0.f;
        for (int o = 8; o; o >>= 1) v += __shfl_xor_sync(~0u, v, o);
        if (tid == 0) red[0] = v;
    }
    __syncthreads();
    float inv = rsqrtf(red[0] * (1.f / HID) + 1e-5f);
#pragma unroll
    for (int k = 0; k < 4; k++) {
        int c = tid + k * 512;
        out[b * HID + c] = (vals[k] - mean) * inv * gg[c] + bb[c];
    }
}

// ---- dual-batch GEMV: warp per row, reads W row once, dots with both x rows ----
// mode 0: store; mode 1: exact-GELU then store; mode 2: out[row] += dot (residual)
__global__ void gemv_kernel(const float* __restrict__ W, const float* __restrict__ x,
                            float* __restrict__ out, int rows, int K, int mode) {
    int row = (blockIdx.x * blockDim.x + threadIdx.x) >> 5;
    int lane = threadIdx.x & 31;
    if (row >= rows) return;
    const float4* wr = (const float4*)(W + (size_t)row * K);
    const float4* x0 = (const float4*)x;
    const float4* x1 = (const float4*)(x + K);
    int n4 = K >> 2;
    float a0 = 0.f, a1 = 0.f;
#pragma unroll 4
    for (int i = lane; i < n4; i += 32) {
        float4 w4 = __ldg(wr + i);
        float4 p0 = __ldg(x0 + i);
        float4 p1 = __ldg(x1 + i);
        a0 += w4.x * p0.x + w4.y * p0.y + w4.z * p0.z + w4.w * p0.w;
        a1 += w4.x * p1.x + w4.y * p1.y + w4.z * p1.z + w4.w * p1.w;
    }
    for (int o = 16; o; o >>= 1) {
        a0 += __shfl_xor_sync(~0u, a0, o);
        a1 += __shfl_xor_sync(~0u, a1, o);
    }
    if (lane == 0) {
        if (mode == 1) {
            a0 = 0.5f * a0 * (1.f + erff(a0 * 0.70710678118654752f));
            a1 = 0.5f * a1 * (1.f + erff(a1 * 0.70710678118654752f));
        }
        if (mode == 2) {
            out[row] += a0;
            out[rows + row] += a1;
        } else {
            out[row] = a0;
            out[rows + row] = a1;
        }
    }
}

// ---- scatter new K/V row into heap (idempotent write into input buffer) ----
__global__ void scatter_kv(float* __restrict__ kheap, float* __restrict__ vheap, int layer) {
    int i = blockIdx.x * blockDim.x + threadIdx.x;
    if (i >= NB * NH * DH) return;
    int d = i & (DH - 1);
    int h = (i >> 7) & (NH - 1);
    int b = i >> 11;
    int wpos = (layer == 0) ? SEQ : (SEQ + 1 + (layer - 1) * RR + RR - 1);
    size_t off = ((size_t)(b * NH + h) * PHEAP + wpos) * DH + d;
    kheap[off] = g_qkv[b * Q3H + h * 384 + 128 + d];
    vheap[off] = g_qkv[b * Q3H + h * 384 + 256 + d];
}

// ---- split-K attention, partial softmax per split ----
// grid: (NB*NH, SPLITS), block 256
__global__ void attn_partial(const float* __restrict__ kheap, const float* __restrict__ vheap,
                             const float* __restrict__ koff, const float* __restrict__ voff,
                             int layer) {
    int bh = blockIdx.x;
    int split = blockIdx.y;
    int b = bh >> 4, h = bh & 15;
    int j0 = split * CHUNK;
    int cnt = min(CHUNK, NKEY - j0);
    __shared__ __align__(16) float sq[DH];
    __shared__ float sc[CHUNK + 3];
    __shared__ float red[8];
    __shared__ __align__(16) float sv[8 * DH];
    int tid = threadIdx.x;
    int lane = tid & 31, w = tid >> 5;
    if (tid < DH) sq[tid] = g_qkv[b * Q3H + h * 384 + tid];
    __syncthreads();
    size_t heap_base = (size_t)(b * NH + h) * PHEAP;
    size_t off_base = (size_t)(((layer - 1) * NB + b) * NH + h) * OFFR;  // only used layer>=1
    int rs = (layer >= 1) ? (layer - 1) * RR : 0;
    float4 q4 = ((const float4*)sq)[lane];

    // -- score pass (reads K) --
    for (int j = w; j < cnt; j += 8) {
        int gj = j0 + j;
        const float* krow;
        if (layer == 0)      krow = kheap + (heap_base + gj) * DH;
        else if (gj < RR)    krow = kheap + (heap_base + rs + gj) * DH;
        else                 krow = koff + (off_base + (gj - RR)) * DH;
        float4 k4 = __ldg((const float4*)krow + lane);
        float s = k4.x * q4.x + k4.y * q4.y + k4.z * q4.z + k4.w * q4.w;
        for (int o = 16; o; o >>= 1) s += __shfl_xor_sync(~0u, s, o);
        if (lane == 0) sc[j] = s * 0.088388347648318447f;  // 1/sqrt(128)
    }
    __syncthreads();

    // -- block max --
    float lm = -1e30f;
    for (int j = tid; j < cnt; j += 256) lm = fmaxf(lm, sc[j]);
    for (int o = 16; o; o >>= 1) lm = fmaxf(lm, __shfl_xor_sync(~0u, lm, o));
    if (lane == 0) red[w] = lm;
    __syncthreads();
    float m = fmaxf(fmaxf(fmaxf(red[0], red[1]), fmaxf(red[2], red[3])),
                    fmaxf(fmaxf(red[4], red[5]), fmaxf(red[6], red[7])));

    // -- exp & sum --
    float ls = 0.f;
    for (int j = tid; j < cnt; j += 256) {
        float p = expf(sc[j] - m);
        sc[j] = p;
        ls += p;
    }
    for (int o = 16; o; o >>= 1) ls += __shfl_xor_sync(~0u, ls, o);
    __syncthreads();           // all reads of red[] for m done; sc[] updates visible
    if (lane == 0) red[w] = ls;
    __syncthreads();
    float lsum = red[0] + red[1] + red[2] + red[3] + red[4] + red[5] + red[6] + red[7];

    // -- V pass --
    float4 acc = make_float4(0.f, 0.f, 0.f, 0.f);
    for (int j = w; j < cnt; j += 8) {
        int gj = j0 + j;
        const float* vrow;
        if (layer == 0)      vrow = vheap + (heap_base + gj) * DH;
        else if (gj < RR)    vrow = vheap + (heap_base + rs + gj) * DH;
        else                 vrow = voff + (off_base + (gj - RR)) * DH;
        float4 v4 = __ldg((const float4*)vrow + lane);
        float p = sc[j];
        acc.x += p * v4.x; acc.y += p * v4.y; acc.z += p * v4.z; acc.w += p * v4.w;
    }
    ((float4*)(sv + w * DH))[lane] = acc;
    __syncthreads();
    float* outp = g_part + (size_t)(bh * SPLITS + split) * (DH + 2);
    if (tid < DH) {
        float s = 0.f;
#pragma unroll
        for (int ww = 0; ww < 8; ww++) s += sv[ww * DH + tid];
        outp[2 + tid] = s;
    }
    if (tid == 0) { outp[0] = m; outp[1] = lsum; }
}

// ---- combine split partials, add residual into g_x ----
__global__ void attn_combine() {
    int bh = blockIdx.x;
    int tid = threadIdx.x;  // 128
    __shared__ float sm[SPLITS], slr[SPLITS];
    if (tid < SPLITS) {
        const float* pp = g_part + (size_t)(bh * SPLITS + tid) * (DH + 2);
        sm[tid] = pp[0];
        slr[tid] = pp[1];
    }
    __syncthreads();
    float M = -1e30f;
#pragma unroll
    for (int s = 0; s < SPLITS; s++) M = fmaxf(M, sm[s]);
    float L = 0.f, o = 0.f;
#pragma unroll
    for (int s = 0; s < SPLITS; s++) {
        float wgt = expf(sm[s] - M);
        L += slr[s] * wgt;
        o += g_part[(size_t)(bh * SPLITS + s) * (DH + 2) + 2 + tid] * wgt;
    }
    int b = bh >> 4, h = bh & 15;
    g_x[b * HID + h * DH + tid] += o / L;
}

// ---- final softmax over vocab: grid=NB, block=1024 ----
__global__ void softmax_kernel(float* __restrict__ outp) {
    int b = blockIdx.x;
    int tid = threadIdx.x;
    __shared__ float red[32];
    const float* lg = g_logits + b * NV;
    float m = -1e30f;
    for (int i = tid; i < NV; i += 1024) m = fmaxf(m, __ldg(lg + i));
    for (int o = 16; o; o >>= 1) m = fmaxf(m, __shfl_xor_sync(~0u, m, o));
    if ((tid & 31) == 0) red[tid >> 5] = m;
    __syncthreads();
    if (tid < 32) {
        float v = red[tid];
        for (int o = 16; o; o >>= 1) v = fmaxf(v, __shfl_xor_sync(~0u, v, o));
        if (tid == 0) red[0] = v;
    }
    __syncthreads();
    float M = red[0];
    __syncthreads();
    float s = 0.f;
    for (int i = tid; i < NV; i += 1024) s += expf(__ldg(lg + i) - M);
    for (int o = 16; o; o >>= 1) s += __shfl_xor_sync(~0u, s, o);
    if ((tid & 31) == 0) red[tid >> 5] = s;
    __syncthreads();
    if (tid < 32) {
        float v = red[tid];
        for (int o = 16; o; o >>= 1) v += __shfl_xor_sync(~0u, v, o);
        if (tid == 0) red[0] = v;
    }
    __syncthreads();
    float inv = 1.f / red[0];
    for (int i = tid; i < NV; i += 1024) outp[b * NV + i] = expf(__ldg(lg + i) - M) * inv;
}

extern "C" void kernel_launch(void* const* d_in, const int* in_sizes, int n_in,
                              void* d_out, int out_size) {
    const float* x      = (const float*)d_in[0];
    const float* qkv_w  = (const float*)d_in[1];
    const float* ffn1_w = (const float*)d_in[2];
    const float* ffn2_w = (const float*)d_in[3];
    const float* out_w  = (const float*)d_in[4];
    const float* ln_g   = (const float*)d_in[5];
    const float* ln_b   = (const float*)d_in[6];
    float* kheap        = (float*)d_in[7];
    float* vheap        = (float*)d_in[8];
    const float* koff   = (const float*)d_in[9];
    const float* voff   = (const float*)d_in[10];
    (void)in_sizes; (void)n_in; (void)out_size;

    float *p_x, *p_xn, *p_qkv, *p_h1, *p_logits;
    cudaGetSymbolAddress((void**)&p_x, g_x);
    cudaGetSymbolAddress((void**)&p_xn, g_xn);
    cudaGetSymbolAddress((void**)&p_qkv, g_qkv);
    cudaGetSymbolAddress((void**)&p_h1, g_h1);
    cudaGetSymbolAddress((void**)&p_logits, g_logits);

    pe_add_kernel<<<(NB * HID + 255) / 256, 256>>>(x);

    for (int l = 0; l < NL; l++) {
        ln_kernel<<<NB, 512>>>(p_x, p_xn, ln_g, ln_b);
        gemv_kernel<<<Q3H / 8, 256>>>(qkv_w + (size_t)l * Q3H * HID, p_xn, p_qkv, Q3H, HID, 0);
        scatter_kv<<<(NB * NH * DH + 255) / 256, 256>>>(kheap, vheap, l);
        dim3 ag(NB * NH, SPLITS);
        attn_partial<<<ag, 256>>>(kheap, vheap, koff, voff, l);
        attn_combine<<<NB * NH, 128>>>();
        ln_kernel<<<NB, 512>>>(p_x, p_xn, ln_g, ln_b);
        gemv_kernel<<<FF / 8, 256>>>(ffn1_w + (size_t)l * FF * HID, p_xn, p_h1, FF, HID, 1);
        gemv_kernel<<<HID / 8, 256>>>(ffn2_w + (size_t)l * HID * FF, p_h1, p_x, HID, FF, 2);
    }

    ln_kernel<<<NB, 512>>>(p_x, p_xn, ln_g, ln_b);
    gemv_kernel<<<NV / 8, 256>>>(out_w, p_xn, p_logits, NV, HID, 0);
    softmax_kernel<<<NB, 1024>>>((float*)d_out);
}

// round 3
// speedup vs baseline: 1.0663x; 1.0663x over previous
#include <cuda_runtime.h>
#include <math.h>

// ---- static problem dims ----
#define NB 2
#define HID 2048
#define NH 16
#define DH 128
#define NL 8
#define NV 32000
#define SEQ 2048
#define OFFR 1024
#define RR 1025
#define PHEAP 11272
#define Q3H 6144
#define FF 8192
#define NKEY 2049
#define SPLITS 16
#define CHUNK 129      // ceil(2049/16)

#define M_QKV 0
#define M_GELU 1
#define M_PLAIN 2

// ---- scratch (device globals: no allocation allowed) ----
__device__ float g_x[NB * HID];
__device__ float g_qkv[NB * Q3H];
__device__ float g_h1[NB * FF];
__device__ float g_part[NB * NH * SPLITS * (DH + 2)];
__device__ float g_logits[NB * NV];

// ---- x + positional encoding (pos = 2048, static) ----
__global__ void pe_add_kernel(const float* __restrict__ xin) {
    int i = blockIdx.x * blockDim.x + threadIdx.x;
    if (i >= NB * HID) return;
    int c = i % HID;
    int half = c >> 1;
    double div = exp(-log(10000.0) * (2.0 * half) / (double)HID);
    double ang = (double)SEQ * div;
    float pe = (c & 1) ? (float)cos(ang) : (float)sin(ang);
    g_x[i] = xin[i] + pe;
}

// ---- block reduction over 512 threads (16 warps) ----
__device__ __forceinline__ float blk_reduce(float v, float* red, int tid) {
    int lane = tid & 31, w = tid >> 5;
    for (int o = 16; o; o >>= 1) v += __shfl_xor_sync(~0u, v, o);
    if (lane == 0) red[w] = v;
    __syncthreads();
    if (tid < 32) {
        float t = (tid < 16) ? red[tid] : 0.f;
        for (int o = 8; o; o >>= 1) t += __shfl_xor_sync(~0u, t, o);
        if (tid == 0) red[0] = t;
    }
    __syncthreads();
    float r = red[0];
    __syncthreads();
    return r;
}

// ---- fused LayerNorm + dual-batch GEMV (K = HID fixed) ----
// 512 threads = 16 warps = 16 rows/block. LN(g_x) computed per-block into shared,
// then warp-per-row dot against both batch rows of xn.
// mode: M_QKV (store + scatter K/V into heap), M_GELU (exact gelu), M_PLAIN.
__global__ void lngemv_kernel(const float* __restrict__ W,
                              const float* __restrict__ gg, const float* __restrict__ bb,
                              float* __restrict__ out, int rows, int mode,
                              float* __restrict__ kheap, float* __restrict__ vheap, int wpos) {
    __shared__ __align__(16) float sxn[NB * HID];
    __shared__ float red[16];
    int tid = threadIdx.x;
#pragma unroll
    for (int b = 0; b < NB; b++) {
        float v[4];
        float s = 0.f;
#pragma unroll
        for (int k = 0; k < 4; k++) { v[k] = g_x[b * HID + tid + k * 512]; s += v[k]; }
        float mean = blk_reduce(s, red, tid) * (1.f / HID);
        float s2 = 0.f;
#pragma unroll
        for (int k = 0; k < 4; k++) { float d = v[k] - mean; s2 += d * d; }
        float inv = rsqrtf(blk_reduce(s2, red, tid) * (1.f / HID) + 1e-5f);
#pragma unroll
        for (int k = 0; k < 4; k++) {
            int c = tid + k * 512;
            sxn[b * HID + c] = (v[k] - mean) * inv * gg[c] + bb[c];
        }
    }
    __syncthreads();
    int w = tid >> 5, lane = tid & 31;
    int row = blockIdx.x * 16 + w;
    if (row >= rows) return;
    const float4* wr = (const float4*)(W + (size_t)row * HID);
    const float4* x0 = (const float4*)sxn;
    const float4* x1 = (const float4*)(sxn + HID);
    float a0 = 0.f, a1 = 0.f;
#pragma unroll 8
    for (int i = lane; i < HID / 4; i += 32) {
        float4 w4 = __ldg(wr + i);
        float4 p0 = x0[i];
        float4 p1 = x1[i];
        a0 += w4.x * p0.x + w4.y * p0.y + w4.z * p0.z + w4.w * p0.w;
        a1 += w4.x * p1.x + w4.y * p1.y + w4.z * p1.z + w4.w * p1.w;
    }
    for (int o = 16; o; o >>= 1) {
        a0 += __shfl_xor_sync(~0u, a0, o);
        a1 += __shfl_xor_sync(~0u, a1, o);
    }
    if (lane == 0) {
        if (mode == M_GELU) {
            a0 = 0.5f * a0 * (1.f + erff(a0 * 0.70710678118654752f));
            a1 = 0.5f * a1 * (1.f + erff(a1 * 0.70710678118654752f));
        }
        out[row] = a0;
        out[rows + row] = a1;
        if (mode == M_QKV) {
            int h = row / 384;
            int t = row - h * 384;
            if (t >= 128) {
                int d = t & 127;
                size_t o0 = ((size_t)(0 * NH + h) * PHEAP + wpos) * DH + d;
                size_t o1 = ((size_t)(1 * NH + h) * PHEAP + wpos) * DH + d;
                if (t < 256) { kheap[o0] = a0; kheap[o1] = a1; }
                else         { vheap[o0] = a0; vheap[o1] = a1; }
            }
        }
    }
}

// ---- FFN2 GEMV (K = FF), residual add into g_x ----
__global__ void ffn2_kernel(const float* __restrict__ W) {
    int tid = threadIdx.x;
    int w = tid >> 5, lane = tid & 31;
    int row = blockIdx.x * 16 + w;
    const float4* wr = (const float4*)(W + (size_t)row * FF);
    const float4* x0 = (const float4*)g_h1;
    const float4* x1 = (const float4*)(g_h1 + FF);
    float a0 = 0.f, a1 = 0.f;
#pragma unroll 8
    for (int i = lane; i < FF / 4; i += 32) {
        float4 w4 = __ldg(wr + i);
        float4 p0 = __ldg(x0 + i);
        float4 p1 = __ldg(x1 + i);
        a0 += w4.x * p0.x + w4.y * p0.y + w4.z * p0.z + w4.w * p0.w;
        a1 += w4.x * p1.x + w4.y * p1.y + w4.z * p1.z + w4.w * p1.w;
    }
    for (int o = 16; o; o >>= 1) {
        a0 += __shfl_xor_sync(~0u, a0, o);
        a1 += __shfl_xor_sync(~0u, a1, o);
    }
    if (lane == 0) {
        g_x[row] += a0;
        g_x[HID + row] += a1;
    }
}

// ---- split-K attention, partial softmax per split: grid (NB*NH, SPLITS), block 256 ----
__global__ void attn_partial(const float* __restrict__ kheap, const float* __restrict__ vheap,
                             const float* __restrict__ koff, const float* __restrict__ voff,
                             int layer) {
    int bh = blockIdx.x;
    int split = blockIdx.y;
    int b = bh >> 4, h = bh & 15;
    int j0 = split * CHUNK;
    int cnt = min(CHUNK, NKEY - j0);
    __shared__ __align__(16) float sq[DH];
    __shared__ float sc[CHUNK + 3];
    __shared__ float red[8];
    __shared__ __align__(16) float sv[8 * DH];
    int tid = threadIdx.x;
    int lane = tid & 31, w = tid >> 5;
    if (tid < DH) sq[tid] = g_qkv[b * Q3H + h * 384 + tid];
    __syncthreads();
    size_t heap_base = (size_t)(b * NH + h) * PHEAP;
    size_t off_base = (size_t)(((layer - 1) * NB + b) * NH + h) * OFFR;
    int rs = (layer >= 1) ? (layer - 1) * RR : 0;
    float4 q4 = ((const float4*)sq)[lane];

    // score pass (K)
    for (int j = w; j < cnt; j += 8) {
        int gj = j0 + j;
        const float* krow;
        if (layer == 0)      krow = kheap + (heap_base + gj) * DH;
        else if (gj < RR)    krow = kheap + (heap_base + rs + gj) * DH;
        else                 krow = koff + (off_base + (gj - RR)) * DH;
        float4 k4 = __ldg((const float4*)krow + lane);
        float s = k4.x * q4.x + k4.y * q4.y + k4.z * q4.z + k4.w * q4.w;
        for (int o = 16; o; o >>= 1) s += __shfl_xor_sync(~0u, s, o);
        if (lane == 0) sc[j] = s * 0.088388347648318447f;
    }
    __syncthreads();

    // block max
    float lm = -1e30f;
    for (int j = tid; j < cnt; j += 256) lm = fmaxf(lm, sc[j]);
    for (int o = 16; o; o >>= 1) lm = fmaxf(lm, __shfl_xor_sync(~0u, lm, o));
    if (lane == 0) red[w] = lm;
    __syncthreads();
    float m = fmaxf(fmaxf(fmaxf(red[0], red[1]), fmaxf(red[2], red[3])),
                    fmaxf(fmaxf(red[4], red[5]), fmaxf(red[6], red[7])));

    // exp & sum
    float ls = 0.f;
    for (int j = tid; j < cnt; j += 256) {
        float p = expf(sc[j] - m);
        sc[j] = p;
        ls += p;
    }
    for (int o = 16; o; o >>= 1) ls += __shfl_xor_sync(~0u, ls, o);
    __syncthreads();
    if (lane == 0) red[w] = ls;
    __syncthreads();
    float lsum = red[0] + red[1] + red[2] + red[3] + red[4] + red[5] + red[6] + red[7];

    // V pass
    float4 acc = make_float4(0.f, 0.f, 0.f, 0.f);
    for (int j = w; j < cnt; j += 8) {
        int gj = j0 + j;
        const float* vrow;
        if (layer == 0)      vrow = vheap + (heap_base + gj) * DH;
        else if (gj < RR)    vrow = vheap + (heap_base + rs + gj) * DH;
        else                 vrow = voff + (off_base + (gj - RR)) * DH;
        float4 v4 = __ldg((const float4*)vrow + lane);
        float p = sc[j];
        acc.x += p * v4.x; acc.y += p * v4.y; acc.z += p * v4.z; acc.w += p * v4.w;
    }
    ((float4*)(sv + w * DH))[lane] = acc;
    __syncthreads();
    float* outp = g_part + (size_t)(bh * SPLITS + split) * (DH + 2);
    if (tid < DH) {
        float s = 0.f;
#pragma unroll
        for (int ww = 0; ww < 8; ww++) s += sv[ww * DH + tid];
        outp[2 + tid] = s;
    }
    if (tid == 0) { outp[0] = m; outp[1] = lsum; }
}

// ---- combine split partials, add residual into g_x ----
__global__ void attn_combine() {
    int bh = blockIdx.x;
    int tid = threadIdx.x;  // 128
    __shared__ float sm[SPLITS], slr[SPLITS];
    if (tid < SPLITS) {
        const float* pp = g_part + (size_t)(bh * SPLITS + tid) * (DH + 2);
        sm[tid] = pp[0];
        slr[tid] = pp[1];
    }
    __syncthreads();
    float M = -1e30f;
#pragma unroll
    for (int s = 0; s < SPLITS; s++) M = fmaxf(M, sm[s]);
    float L = 0.f, o = 0.f;
#pragma unroll
    for (int s = 0; s < SPLITS; s++) {
        float wgt = expf(sm[s] - M);
        L += slr[s] * wgt;
        o += g_part[(size_t)(bh * SPLITS + s) * (DH + 2) + 2 + tid] * wgt;
    }
    int b = bh >> 4, h = bh & 15;
    g_x[b * HID + h * DH + tid] += o / L;
}

// ---- final softmax over vocab: grid=NB, block=1024 ----
__global__ void softmax_kernel(float* __restrict__ outp) {
    int b = blockIdx.x;
    int tid = threadIdx.x;
    __shared__ float red[32];
    const float* lg = g_logits + b * NV;
    float m = -1e30f;
    for (int i = tid; i < NV; i += 1024) m = fmaxf(m, __ldg(lg + i));
    for (int o = 16; o; o >>= 1) m = fmaxf(m, __shfl_xor_sync(~0u, m, o));
    if ((tid & 31) == 0) red[tid >> 5] = m;
    __syncthreads();
    if (tid < 32) {
        float v = red[tid];
        for (int o = 16; o; o >>= 1) v = fmaxf(v, __shfl_xor_sync(~0u, v, o));
        if (tid == 0) red[0] = v;
    }
    __syncthreads();
    float M = red[0];
    __syncthreads();
    float s = 0.f;
    for (int i = tid; i < NV; i += 1024) s += expf(__ldg(lg + i) - M);
    for (int o = 16; o; o >>= 1) s += __shfl_xor_sync(~0u, s, o);
    if ((tid & 31) == 0) red[tid >> 5] = s;
    __syncthreads();
    if (tid < 32) {
        float v = red[tid];
        for (int o = 16; o; o >>= 1) v += __shfl_xor_sync(~0u, v, o);
        if (tid == 0) red[0] = v;
    }
    __syncthreads();
    float inv = 1.f / red[0];
    for (int i = tid; i < NV; i += 1024) outp[b * NV + i] = expf(__ldg(lg + i) - M) * inv;
}

extern "C" void kernel_launch(void* const* d_in, const int* in_sizes, int n_in,
                              void* d_out, int out_size) {
    const float* x      = (const float*)d_in[0];
    const float* qkv_w  = (const float*)d_in[1];
    const float* ffn1_w = (const float*)d_in[2];
    const float* ffn2_w = (const float*)d_in[3];
    const float* out_w  = (const float*)d_in[4];
    const float* ln_g   = (const float*)d_in[5];
    const float* ln_b   = (const float*)d_in[6];
    float* kheap        = (float*)d_in[7];
    float* vheap        = (float*)d_in[8];
    const float* koff   = (const float*)d_in[9];
    const float* voff   = (const float*)d_in[10];
    (void)in_sizes; (void)n_in; (void)out_size;

    float *p_qkv, *p_h1, *p_logits;
    cudaGetSymbolAddress((void**)&p_qkv, g_qkv);
    cudaGetSymbolAddress((void**)&p_h1, g_h1);
    cudaGetSymbolAddress((void**)&p_logits, g_logits);

    pe_add_kernel<<<(NB * HID + 255) / 256, 256>>>(x);

    for (int l = 0; l < NL; l++) {
        int wpos = SEQ + l * RR;  // l=0: 2048 ; l>=1: S+1+(l-1)*R+R-1
        lngemv_kernel<<<Q3H / 16, 512>>>(qkv_w + (size_t)l * Q3H * HID, ln_g, ln_b,
                                         p_qkv, Q3H, M_QKV, kheap, vheap, wpos);
        dim3 ag(NB * NH, SPLITS);
        attn_partial<<<ag, 256>>>(kheap, vheap, koff, voff, l);
        attn_combine<<<NB * NH, 128>>>();
        lngemv_kernel<<<FF / 16, 512>>>(ffn1_w + (size_t)l * FF * HID, ln_g, ln_b,
                                        p_h1, FF, M_GELU, nullptr, nullptr, 0);
        ffn2_kernel<<<HID / 16, 512>>>(ffn2_w + (size_t)l * HID * FF);
    }

    lngemv_kernel<<<NV / 16, 512>>>(out_w, ln_g, ln_b, p_logits, NV, M_PLAIN,
                                    nullptr, nullptr, 0);
    softmax_kernel<<<NB, 1024>>>((float*)d_out);
}

// round 5
// speedup vs baseline: 1.1083x; 1.0394x over previous
#include <cuda_runtime.h>
#include <math.h>

// ---- static problem dims ----
#define NB 2
#define HID 2048
#define NH 16
#define DH 128
#define NL 8
#define NV 32000
#define SEQ 2048
#define OFFR 1024
#define RR 1025
#define PHEAP 11272
#define Q3H 6144
#define FF 8192
#define NKEY 2049
#define SPLITS 16
#define CHUNK 129          // ceil(2049/16)

#define NBLK 148
#define NTHR 1024
#define NWARP 32
#define TOTW (NBLK * NWARP)   // 4736
#define VSLICE 217            // ceil(32000/148)

// ---- scratch (device globals; zero-init) ----
__device__ float g_x[NB * HID];
__device__ float g_qkv[NB * Q3H];
__device__ float g_h1[NB * FF];
__device__ float g_part[NB * NH * SPLITS * (DH + 2)];
__device__ float g_logits[NB * NV];
__device__ float g_sm[NB * NBLK * 2];     // softmax partials (m, s)
__device__ unsigned g_cnt;
__device__ volatile unsigned g_gen;

// ---- grid-wide barrier (all 148 blocks co-resident by construction) ----
__device__ __forceinline__ void gbar() {
    __syncthreads();
    if (threadIdx.x == 0) {
        unsigned gen = g_gen;
        __threadfence();
        if (atomicAdd(&g_cnt, 1u) == NBLK - 1) {
            g_cnt = 0;
            __threadfence();
            g_gen = gen + 1;
        } else {
            while (g_gen == gen) __nanosleep(32);
            __threadfence();
        }
    }
    __syncthreads();
}

// ---- block reductions over 1024 threads ----
__device__ __forceinline__ float blk_sum(float v, float* red) {
    int tid = threadIdx.x, lane = tid & 31, w = tid >> 5;
    for (int o = 16; o; o >>= 1) v += __shfl_xor_sync(~0u, v, o);
    if (lane == 0) red[w] = v;
    __syncthreads();
    if (tid < 32) {
        float t = red[tid];
        for (int o = 16; o; o >>= 1) t += __shfl_xor_sync(~0u, t, o);
        if (tid == 0) red[0] = t;
    }
    __syncthreads();
    float r = red[0];
    __syncthreads();
    return r;
}
__device__ __forceinline__ float blk_max(float v, float* red) {
    int tid = threadIdx.x, lane = tid & 31, w = tid >> 5;
    for (int o = 16; o; o >>= 1) v = fmaxf(v, __shfl_xor_sync(~0u, v, o));
    if (lane == 0) red[w] = v;
    __syncthreads();
    if (tid < 32) {
        float t = red[tid];
        for (int o = 16; o; o >>= 1) t = fmaxf(t, __shfl_xor_sync(~0u, t, o));
        if (tid == 0) red[0] = t;
    }
    __syncthreads();
    float r = red[0];
    __syncthreads();
    return r;
}

// ---- warp dual-batch dot: weights via __ldg (immutable), x via plain loads ----
__device__ __forceinline__ void warp_dot2(const float4* wr, const float4* x0,
                                          const float4* x1, int n4, int lane,
                                          float& a0, float& a1) {
    a0 = 0.f; a1 = 0.f;
#pragma unroll 8
    for (int i = lane; i < n4; i += 32) {
        float4 w4 = __ldg(wr + i);
        float4 p0 = x0[i];
        float4 p1 = x1[i];
        a0 += w4.x * p0.x + w4.y * p0.y + w4.z * p0.z + w4.w * p0.w;
        a1 += w4.x * p1.x + w4.y * p1.y + w4.z * p1.z + w4.w * p1.w;
    }
    for (int o = 16; o; o >>= 1) {
        a0 += __shfl_xor_sync(~0u, a0, o);
        a1 += __shfl_xor_sync(~0u, a1, o);
    }
}

__global__ void __launch_bounds__(NTHR, 1)
mega_kernel(const float* xin, const float* qkv_w, const float* ffn1_w,
            const float* ffn2_w, const float* out_w, const float* ln_g,
            const float* ln_b, float* kheap, float* vheap,
            const float* koff, const float* voff, float* out) {
    __shared__ __align__(16) float s_xn[NB * HID];   // 16 KB
    __shared__ float s_red[32];
    __shared__ __align__(16) float s_q[4][DH];
    __shared__ float s_sc[4][CHUNK + 3];
    __shared__ float s_r8[4][8];
    __shared__ __align__(16) float s_v[4][8 * DH];   // 16 KB

    int tid = threadIdx.x, bid = blockIdx.x;
    int w = tid >> 5, lane = tid & 31;

    // ---------- phase: x + positional encoding (pos = SEQ) ----------
    {
        int i = bid * NTHR + tid;
        if (i < NB * HID) {
            int c = i & (HID - 1);
            int half = c >> 1;
            double div = exp(-log(10000.0) * (2.0 * half) / (double)HID);
            double ang = (double)SEQ * div;
            float pe = (c & 1) ? (float)cos(ang) : (float)sin(ang);
            g_x[i] = xin[i] + pe;
        }
    }
    gbar();

    for (int l = 0; l < NL; l++) {
        // ---------- LN + QKV gemv (+ KV scatter into heap) ----------
        {
#pragma unroll
            for (int b = 0; b < NB; b++) {
                float v0 = g_x[b * HID + tid];
                float v1 = g_x[b * HID + tid + 1024];
                float mean = blk_sum(v0 + v1, s_red) * (1.f / HID);
                float d0 = v0 - mean, d1 = v1 - mean;
                float inv = rsqrtf(blk_sum(d0 * d0 + d1 * d1, s_red) * (1.f / HID) + 1e-5f);
                s_xn[b * HID + tid] = d0 * inv * __ldg(ln_g + tid) + __ldg(ln_b + tid);
                s_xn[b * HID + tid + 1024] = d1 * inv * __ldg(ln_g + tid + 1024) + __ldg(ln_b + tid + 1024);
            }
            __syncthreads();
            const float* W = qkv_w + (size_t)l * Q3H * HID;
            int wpos = SEQ + l * RR;
            for (int r = w * NBLK + bid; r < Q3H; r += TOTW) {
                float a0, a1;
                warp_dot2((const float4*)(W + (size_t)r * HID), (const float4*)s_xn,
                          (const float4*)(s_xn + HID), HID / 4, lane, a0, a1);
                if (lane == 0) {
                    g_qkv[r] = a0;
                    g_qkv[Q3H + r] = a1;
                    int h = r / 384;
                    int t = r - h * 384;
                    if (t >= 128) {
                        int d = t & 127;
                        size_t o0 = ((size_t)h * PHEAP + wpos) * DH + d;
                        size_t o1 = ((size_t)(NH + h) * PHEAP + wpos) * DH + d;
                        if (t < 256) { kheap[o0] = a0; kheap[o1] = a1; }
                        else         { vheap[o0] = a0; vheap[o1] = a1; }
                    }
                }
            }
        }
        gbar();

        // ---------- attention partials: 512 units over 592 groups ----------
        if (bid < (NB * NH * SPLITS) / 4) {   // bid < 128: all 4 groups active
            int grp = tid >> 8;
            int gt = tid & 255;
            int lw = gt >> 5, ll = gt & 31;
            int g = bid * 4 + grp;            // unit = bh*SPLITS + split
            int bh = g >> 4, split = g & 15;
            int b = bh >> 4, h = bh & 15;
            int j0 = split * CHUNK;
            int cnt = min(CHUNK, NKEY - j0);
            if (gt < DH) s_q[grp][gt] = g_qkv[b * Q3H + h * 384 + gt];
            __syncthreads();
            size_t heap_base = (size_t)(b * NH + h) * PHEAP;
            size_t off_base = (size_t)(((l - 1) * NB + b) * NH + h) * OFFR;
            int rs = (l >= 1) ? (l - 1) * RR : 0;
            float4 q4 = ((const float4*)s_q[grp])[ll];

            for (int j = lw; j < cnt; j += 8) {
                int gj = j0 + j;
                const float* krow;
                if (l == 0)       krow = kheap + (heap_base + gj) * DH;
                else if (gj < RR) krow = kheap + (heap_base + rs + gj) * DH;
                else              krow = koff + (off_base + (gj - RR)) * DH;
                float4 k4 = ((const float4*)krow)[ll];
                float s = k4.x * q4.x + k4.y * q4.y + k4.z * q4.z + k4.w * q4.w;
                for (int o = 16; o; o >>= 1) s += __shfl_xor_sync(~0u, s, o);
                if (ll == 0) s_sc[grp][j] = s * 0.088388347648318447f;
            }
            __syncthreads();

            float lm = -1e30f;
            for (int j = gt; j < cnt; j += 256) lm = fmaxf(lm, s_sc[grp][j]);
            for (int o = 16; o; o >>= 1) lm = fmaxf(lm, __shfl_xor_sync(~0u, lm, o));
            if (ll == 0) s_r8[grp][lw] = lm;
            __syncthreads();
            float m = fmaxf(fmaxf(fmaxf(s_r8[grp][0], s_r8[grp][1]), fmaxf(s_r8[grp][2], s_r8[grp][3])),
                            fmaxf(fmaxf(s_r8[grp][4], s_r8[grp][5]), fmaxf(s_r8[grp][6], s_r8[grp][7])));

            float ls = 0.f;
            for (int j = gt; j < cnt; j += 256) {
                float p = expf(s_sc[grp][j] - m);
                s_sc[grp][j] = p;
                ls += p;
            }
            for (int o = 16; o; o >>= 1) ls += __shfl_xor_sync(~0u, ls, o);
            __syncthreads();
            if (ll == 0) s_r8[grp][lw] = ls;
            __syncthreads();
            float lsum = s_r8[grp][0] + s_r8[grp][1] + s_r8[grp][2] + s_r8[grp][3] +
                         s_r8[grp][4] + s_r8[grp][5] + s_r8[grp][6] + s_r8[grp][7];

            float4 acc = make_float4(0.f, 0.f, 0.f, 0.f);
            for (int j = lw; j < cnt; j += 8) {
                int gj = j0 + j;
                const float* vrow;
                if (l == 0)       vrow = vheap + (heap_base + gj) * DH;
                else if (gj < RR) vrow = vheap + (heap_base + rs + gj) * DH;
                else              vrow = voff + (off_base + (gj - RR)) * DH;
                float4 v4 = ((const float4*)vrow)[ll];
                float p = s_sc[grp][j];
                acc.x += p * v4.x; acc.y += p * v4.y; acc.z += p * v4.z; acc.w += p * v4.w;
            }
            ((float4*)(s_v[grp] + lw * DH))[ll] = acc;
            __syncthreads();
            float* outp = g_part + (size_t)g * (DH + 2);
            if (gt < DH) {
                float s = 0.f;
#pragma unroll
                for (int ww = 0; ww < 8; ww++) s += s_v[grp][ww * DH + gt];
                outp[2 + gt] = s;
            }
            if (gt == 0) { outp[0] = m; outp[1] = lsum; }
        }
        gbar();

        // ---------- combine splits, residual add ----------
        if (bid < NB * NH) {
            if (tid < SPLITS) {
                s_q[0][tid] = g_part[(size_t)(bid * SPLITS + tid) * (DH + 2)];
                s_q[1][tid] = g_part[(size_t)(bid * SPLITS + tid) * (DH + 2) + 1];
            }
            __syncthreads();
            if (tid < DH) {
                float M = -1e30f;
#pragma unroll
                for (int s = 0; s < SPLITS; s++) M = fmaxf(M, s_q[0][s]);
                float L = 0.f, o = 0.f;
#pragma unroll
                for (int s = 0; s < SPLITS; s++) {
                    float wgt = expf(s_q[0][s] - M);
                    L += s_q[1][s] * wgt;
                    o += g_part[(size_t)(bid * SPLITS + s) * (DH + 2) + 2 + tid] * wgt;
                }
                int b = bid >> 4, h = bid & 15;
                g_x[b * HID + h * DH + tid] += o / L;
            }
        }
        gbar();

        // ---------- LN + FFN1 (exact gelu) ----------
        {
#pragma unroll
            for (int b = 0; b < NB; b++) {
                float v0 = g_x[b * HID + tid];
                float v1 = g_x[b * HID + tid + 1024];
                float mean = blk_sum(v0 + v1, s_red) * (1.f / HID);
                float d0 = v0 - mean, d1 = v1 - mean;
                float inv = rsqrtf(blk_sum(d0 * d0 + d1 * d1, s_red) * (1.f / HID) + 1e-5f);
                s_xn[b * HID + tid] = d0 * inv * __ldg(ln_g + tid) + __ldg(ln_b + tid);
                s_xn[b * HID + tid + 1024] = d1 * inv * __ldg(ln_g + tid + 1024) + __ldg(ln_b + tid + 1024);
            }
            __syncthreads();
            const float* W = ffn1_w + (size_t)l * FF * HID;
            for (int r = w * NBLK + bid; r < FF; r += TOTW) {
                float a0, a1;
                warp_dot2((const float4*)(W + (size_t)r * HID), (const float4*)s_xn,
                          (const float4*)(s_xn + HID), HID / 4, lane, a0, a1);
                if (lane == 0) {
                    g_h1[r]      = 0.5f * a0 * (1.f + erff(a0 * 0.70710678118654752f));
                    g_h1[FF + r] = 0.5f * a1 * (1.f + erff(a1 * 0.70710678118654752f));
                }
            }
        }
        gbar();

        // ---------- FFN2 (K = FF), residual add ----------
        {
            const float* W = ffn2_w + (size_t)l * HID * FF;
            for (int r = w * NBLK + bid; r < HID; r += TOTW) {
                float a0, a1;
                warp_dot2((const float4*)(W + (size_t)r * FF), (const float4*)g_h1,
                          (const float4*)(g_h1 + FF), FF / 4, lane, a0, a1);
                if (lane == 0) {
                    g_x[r] += a0;
                    g_x[HID + r] += a1;
                }
            }
        }
        gbar();
    }

    // ---------- LN + logits gemv ----------
    {
#pragma unroll
        for (int b = 0; b < NB; b++) {
            float v0 = g_x[b * HID + tid];
            float v1 = g_x[b * HID + tid + 1024];
            float mean = blk_sum(v0 + v1, s_red) * (1.f / HID);
            float d0 = v0 - mean, d1 = v1 - mean;
            float inv = rsqrtf(blk_sum(d0 * d0 + d1 * d1, s_red) * (1.f / HID) + 1e-5f);
            s_xn[b * HID + tid] = d0 * inv * __ldg(ln_g + tid) + __ldg(ln_b + tid);
            s_xn[b * HID + tid + 1024] = d1 * inv * __ldg(ln_g + tid + 1024) + __ldg(ln_b + tid + 1024);
        }
        __syncthreads();
        for (int r = w * NBLK + bid; r < NV; r += TOTW) {
            float a0, a1;
            warp_dot2((const float4*)(out_w + (size_t)r * HID), (const float4*)s_xn,
                      (const float4*)(s_xn + HID), HID / 4, lane, a0, a1);
            if (lane == 0) {
                g_logits[r] = a0;
                g_logits[NV + r] = a1;
            }
        }
    }
    gbar();

    // ---------- softmax phase A: per-block slice partials ----------
    {
        int start = bid * VSLICE;
        int cnt = min(VSLICE, NV - start);
        if (cnt < 0) cnt = 0;
#pragma unroll
        for (int b = 0; b < NB; b++) {
            const float* lg = g_logits + b * NV + start;
            float m = -1e30f;
            for (int i = tid; i < cnt; i += NTHR) m = fmaxf(m, lg[i]);
            m = blk_max(m, s_red);
            float s = 0.f;
            for (int i = tid; i < cnt; i += NTHR) s += expf(lg[i] - m);
            s = blk_sum(s, s_red);
            if (tid == 0) {
                g_sm[(b * NBLK + bid) * 2]     = m;
                g_sm[(b * NBLK + bid) * 2 + 1] = s;
            }
        }
    }
    gbar();

    // ---------- softmax phase B: global combine + write output ----------
    {
        // load all partials to shared (reuse s_xn)
        if (tid < NB * NBLK * 2) s_xn[tid] = g_sm[tid];
        __syncthreads();
        int start = bid * VSLICE;
        int cnt = min(VSLICE, NV - start);
        if (cnt < 0) cnt = 0;
#pragma unroll
        for (int b = 0; b < NB; b++) {
            float M = -1e30f;
            for (int k = 0; k < NBLK; k++) M = fmaxf(M, s_xn[(b * NBLK + k) * 2]);
            float S = 0.f;
            for (int k = 0; k < NBLK; k++)
                S += s_xn[(b * NBLK + k) * 2 + 1] * expf(s_xn[(b * NBLK + k) * 2] - M);
            float invS = 1.f / S;
            const float* lg = g_logits + b * NV + start;
            float* op = out + b * NV + start;
            for (int i = tid; i < cnt; i += NTHR) op[i] = expf(lg[i] - M) * invS;
        }
    }
}

extern "C" void kernel_launch(void* const* d_in, const int* in_sizes, int n_in,
                              void* d_out, int out_size) {
    const float* x      = (const float*)d_in[0];
    const float* qkv_w  = (const float*)d_in[1];
    const float* ffn1_w = (const float*)d_in[2];
    const float* ffn2_w = (const float*)d_in[3];
    const float* out_w  = (const float*)d_in[4];
    const float* ln_g   = (const float*)d_in[5];
    const float* ln_b   = (const float*)d_in[6];
    float* kheap        = (float*)d_in[7];
    float* vheap        = (float*)d_in[8];
    const float* koff   = (const float*)d_in[9];
    const float* voff   = (const float*)d_in[10];
    (void)in_sizes; (void)n_in; (void)out_size;

    mega_kernel<<<NBLK, NTHR>>>(x, qkv_w, ffn1_w, ffn2_w, out_w, ln_g, ln_b,
                                kheap, vheap, koff, voff, (float*)d_out);
}

// round 6
// speedup vs baseline: 1.2239x; 1.1043x over previous
#include <cuda_runtime.h>
#include <math.h>

// ---- static problem dims ----
#define NB 2
#define HID 2048
#define NH 16
#define DH 128
#define NL 8
#define NV 32000
#define SEQ 2048
#define OFFR 1024
#define RR 1025
#define PHEAP 11272
#define Q3H 6144
#define FF 8192
#define NKEY 2049
#define SPLITS 18
#define CHUNK 114          // ceil(2049/18)

#define NBLK 148
#define NTHR 1024
#define NWARP 32
#define TOTW (NBLK * NWARP)   // 4736
#define VSLICE 217            // ceil(32000/148)

// ---- scratch (device globals; zero-init) ----
__device__ float g_x[NB * HID];
__device__ float g_qkv[NB * Q3H];
__device__ float g_h1[NB * FF];
__device__ float g_qp[2 * NB * Q3H];      // QKV split-K partials [half][b][row]
__device__ float g_fp[2 * NB * HID];      // FFN2 split-K partials [half][b][row]
__device__ float g_part[NB * NH * SPLITS * (DH + 2)];
__device__ float g_logits[NB * NV];
__device__ float g_sm[NB * NBLK * 2];     // softmax partials (m, s)
__device__ unsigned g_cnt;
__device__ volatile unsigned g_gen;

// ---- grid-wide barrier (all 148 blocks co-resident by construction) ----
__device__ __forceinline__ void gbar() {
    __syncthreads();
    if (threadIdx.x == 0) {
        unsigned gen = g_gen;
        __threadfence();
        if (atomicAdd(&g_cnt, 1u) == NBLK - 1) {
            g_cnt = 0;
            __threadfence();
            g_gen = gen + 1;
        } else {
            while (g_gen == gen) __nanosleep(32);
            __threadfence();
        }
    }
    __syncthreads();
}

// ---- block reductions over 1024 threads ----
__device__ __forceinline__ float blk_sum(float v, float* red) {
    int tid = threadIdx.x, lane = tid & 31, w = tid >> 5;
    for (int o = 16; o; o >>= 1) v += __shfl_xor_sync(~0u, v, o);
    if (lane == 0) red[w] = v;
    __syncthreads();
    if (tid < 32) {
        float t = red[tid];
        for (int o = 16; o; o >>= 1) t += __shfl_xor_sync(~0u, t, o);
        if (tid == 0) red[0] = t;
    }
    __syncthreads();
    float r = red[0];
    __syncthreads();
    return r;
}
__device__ __forceinline__ float blk_max(float v, float* red) {
    int tid = threadIdx.x, lane = tid & 31, w = tid >> 5;
    for (int o = 16; o; o >>= 1) v = fmaxf(v, __shfl_xor_sync(~0u, v, o));
    if (lane == 0) red[w] = v;
    __syncthreads();
    if (tid < 32) {
        float t = red[tid];
        for (int o = 16; o; o >>= 1) t = fmaxf(t, __shfl_xor_sync(~0u, t, o));
        if (tid == 0) red[0] = t;
    }
    __syncthreads();
    float r = red[0];
    __syncthreads();
    return r;
}

// ---- warp dual-batch dot; weights streamed with evict-first hint ----
__device__ __forceinline__ void warp_dot2(const float4* wr, const float4* x0,
                                          const float4* x1, int n4, int lane,
                                          float& a0, float& a1) {
    a0 = 0.f; a1 = 0.f;
#pragma unroll 8
    for (int i = lane; i < n4; i += 32) {
        float4 w4 = __ldcs(wr + i);
        float4 p0 = x0[i];
        float4 p1 = x1[i];
        a0 += w4.x * p0.x + w4.y * p0.y + w4.z * p0.z + w4.w * p0.w;
        a1 += w4.x * p1.x + w4.y * p1.y + w4.z * p1.z + w4.w * p1.w;
    }
    for (int o = 16; o; o >>= 1) {
        a0 += __shfl_xor_sync(~0u, a0, o);
        a1 += __shfl_xor_sync(~0u, a1, o);
    }
}

__device__ __forceinline__ void do_ln(const float* __restrict__ ln_g,
                                      const float* __restrict__ ln_b,
                                      float* s_xn, float* s_red) {
    int tid = threadIdx.x;
#pragma unroll
    for (int b = 0; b < NB; b++) {
        float v0 = g_x[b * HID + tid];
        float v1 = g_x[b * HID + tid + 1024];
        float mean = blk_sum(v0 + v1, s_red) * (1.f / HID);
        float d0 = v0 - mean, d1 = v1 - mean;
        float inv = rsqrtf(blk_sum(d0 * d0 + d1 * d1, s_red) * (1.f / HID) + 1e-5f);
        s_xn[b * HID + tid] = d0 * inv * __ldg(ln_g + tid) + __ldg(ln_b + tid);
        s_xn[b * HID + tid + 1024] = d1 * inv * __ldg(ln_g + tid + 1024) + __ldg(ln_b + tid + 1024);
    }
    __syncthreads();
}

__global__ void __launch_bounds__(NTHR, 1)
mega_kernel(const float* xin, const float* qkv_w, const float* ffn1_w,
            const float* ffn2_w, const float* out_w, const float* ln_g,
            const float* ln_b, float* kheap, float* vheap,
            const float* koff, const float* voff, float* out) {
    __shared__ __align__(16) float s_xn[NB * HID];   // 16 KB
    __shared__ float s_red[32];
    __shared__ __align__(16) float s_q[4][DH];
    __shared__ float s_sc[4][CHUNK + 2];
    __shared__ float s_r8[4][8];
    __shared__ __align__(16) float s_v[4][8 * DH];   // 16 KB

    int tid = threadIdx.x, bid = blockIdx.x;
    int w = tid >> 5, lane = tid & 31;
    int widx = w * NBLK + bid;

    // ---------- x + positional encoding (pos = SEQ) ----------
    {
        int i = bid * NTHR + tid;
        if (i < NB * HID) {
            int c = i & (HID - 1);
            int half = c >> 1;
            double div = exp(-log(10000.0) * (2.0 * half) / (double)HID);
            double ang = (double)SEQ * div;
            float pe = (c & 1) ? (float)cos(ang) : (float)sin(ang);
            g_x[i] = xin[i] + pe;
        }
    }
    gbar();

    for (int l = 0; l < NL; l++) {
        // ---------- LN + QKV gemv, split-K x2 ----------
        {
            do_ln(ln_g, ln_b, s_xn, s_red);
            const float* W = qkv_w + (size_t)l * Q3H * HID;
            for (int u = widx; u < 2 * Q3H; u += TOTW) {
                int half = (u >= Q3H) ? 1 : 0;
                int r = u - half * Q3H;
                int c0 = half * (HID / 2);
                float a0, a1;
                warp_dot2((const float4*)(W + (size_t)r * HID + c0),
                          (const float4*)(s_xn + c0),
                          (const float4*)(s_xn + HID + c0), HID / 8, lane, a0, a1);
                if (lane == 0) {
                    g_qp[(half * NB + 0) * Q3H + r] = a0;
                    g_qp[(half * NB + 1) * Q3H + r] = a1;
                }
            }
        }
        gbar();

        // ---------- QKV combine + KV scatter ----------
        {
            int idx = bid * NTHR + tid;
            if (idx < NB * Q3H) {
                int b = (idx >= Q3H) ? 1 : 0;
                int r = idx - b * Q3H;
                float v = g_qp[b * Q3H + r] + g_qp[(NB + b) * Q3H + r];
                g_qkv[b * Q3H + r] = v;
                int h = r / 384;
                int t = r - h * 384;
                if (t >= 128) {
                    int d = t & 127;
                    int wpos = SEQ + l * RR;
                    size_t o0 = ((size_t)(b * NH + h) * PHEAP + wpos) * DH + d;
                    if (t < 256) kheap[o0] = v;
                    else         vheap[o0] = v;
                }
            }
        }
        gbar();

        // ---------- attention partials: 576 units = 144 blocks x 4 groups ----------
        if (bid < (NB * NH * SPLITS) / 4) {   // bid < 144
            int grp = tid >> 8;
            int gt = tid & 255;
            int lw = gt >> 5, ll = gt & 31;
            int g = bid * 4 + grp;            // unit = bh*SPLITS + split
            int bh = g / SPLITS, split = g - bh * SPLITS;
            int b = bh >> 4, h = bh & 15;
            int j0 = split * CHUNK;
            int cnt = min(CHUNK, NKEY - j0);
            if (gt < DH) s_q[grp][gt] = g_qkv[b * Q3H + h * 384 + gt];
            __syncthreads();
            size_t heap_base = (size_t)(b * NH + h) * PHEAP;
            size_t off_base = (size_t)(((l - 1) * NB + b) * NH + h) * OFFR;
            int rs = (l >= 1) ? (l - 1) * RR : 0;
            float4 q4 = ((const float4*)s_q[grp])[ll];

            for (int j = lw; j < cnt; j += 8) {
                int gj = j0 + j;
                const float* krow;
                if (l == 0)       krow = kheap + (heap_base + gj) * DH;
                else if (gj < RR) krow = kheap + (heap_base + rs + gj) * DH;
                else              krow = koff + (off_base + (gj - RR)) * DH;
                float4 k4 = ((const float4*)krow)[ll];
                float s = k4.x * q4.x + k4.y * q4.y + k4.z * q4.z + k4.w * q4.w;
                for (int o = 16; o; o >>= 1) s += __shfl_xor_sync(~0u, s, o);
                if (ll == 0) s_sc[grp][j] = s * 0.088388347648318447f;
            }
            __syncthreads();

            float lm = -1e30f;
            for (int j = gt; j < cnt; j += 256) lm = fmaxf(lm, s_sc[grp][j]);
            for (int o = 16; o; o >>= 1) lm = fmaxf(lm, __shfl_xor_sync(~0u, lm, o));
            if (ll == 0) s_r8[grp][lw] = lm;
            __syncthreads();
            float m = fmaxf(fmaxf(fmaxf(s_r8[grp][0], s_r8[grp][1]), fmaxf(s_r8[grp][2], s_r8[grp][3])),
                            fmaxf(fmaxf(s_r8[grp][4], s_r8[grp][5]), fmaxf(s_r8[grp][6], s_r8[grp][7])));

            float ls = 0.f;
            for (int j = gt; j < cnt; j += 256) {
                float p = expf(s_sc[grp][j] - m);
                s_sc[grp][j] = p;
                ls += p;
            }
            for (int o = 16; o; o >>= 1) ls += __shfl_xor_sync(~0u, ls, o);
            __syncthreads();
            if (ll == 0) s_r8[grp][lw] = ls;
            __syncthreads();
            float lsum = s_r8[grp][0] + s_r8[grp][1] + s_r8[grp][2] + s_r8[grp][3] +
                         s_r8[grp][4] + s_r8[grp][5] + s_r8[grp][6] + s_r8[grp][7];

            float4 acc = make_float4(0.f, 0.f, 0.f, 0.f);
            for (int j = lw; j < cnt; j += 8) {
                int gj = j0 + j;
                const float* vrow;
                if (l == 0)       vrow = vheap + (heap_base + gj) * DH;
                else if (gj < RR) vrow = vheap + (heap_base + rs + gj) * DH;
                else              vrow = voff + (off_base + (gj - RR)) * DH;
                float4 v4 = ((const float4*)vrow)[ll];
                float p = s_sc[grp][j];
                acc.x += p * v4.x; acc.y += p * v4.y; acc.z += p * v4.z; acc.w += p * v4.w;
            }
            ((float4*)(s_v[grp] + lw * DH))[ll] = acc;
            __syncthreads();
            float* outp = g_part + (size_t)g * (DH + 2);
            if (gt < DH) {
                float s = 0.f;
#pragma unroll
                for (int ww = 0; ww < 8; ww++) s += s_v[grp][ww * DH + gt];
                outp[2 + gt] = s;
            }
            if (gt == 0) { outp[0] = m; outp[1] = lsum; }
        }
        gbar();

        // ---------- combine splits, residual add ----------
        if (bid < NB * NH) {
            if (tid < SPLITS) {
                s_q[0][tid] = g_part[(size_t)(bid * SPLITS + tid) * (DH + 2)];
                s_q[1][tid] = g_part[(size_t)(bid * SPLITS + tid) * (DH + 2) + 1];
            }
            __syncthreads();
            if (tid < DH) {
                float M = -1e30f;
#pragma unroll
                for (int s = 0; s < SPLITS; s++) M = fmaxf(M, s_q[0][s]);
                float L = 0.f, o = 0.f;
#pragma unroll
                for (int s = 0; s < SPLITS; s++) {
                    float wgt = expf(s_q[0][s] - M);
                    L += s_q[1][s] * wgt;
                    o += g_part[(size_t)(bid * SPLITS + s) * (DH + 2) + 2 + tid] * wgt;
                }
                int b = bid >> 4, h = bid & 15;
                g_x[b * HID + h * DH + tid] += o / L;
            }
        }
        gbar();

        // ---------- LN + FFN1 (exact gelu) ----------
        {
            do_ln(ln_g, ln_b, s_xn, s_red);
            const float* W = ffn1_w + (size_t)l * FF * HID;
            for (int r = widx; r < FF; r += TOTW) {
                float a0, a1;
                warp_dot2((const float4*)(W + (size_t)r * HID), (const float4*)s_xn,
                          (const float4*)(s_xn + HID), HID / 4, lane, a0, a1);
                if (lane == 0) {
                    g_h1[r]      = 0.5f * a0 * (1.f + erff(a0 * 0.70710678118654752f));
                    g_h1[FF + r] = 0.5f * a1 * (1.f + erff(a1 * 0.70710678118654752f));
                }
            }
        }
        gbar();

        // ---------- FFN2 (K = FF) split-K x2: 4096 units, one pass ----------
        {
            const float* W = ffn2_w + (size_t)l * HID * FF;
            if (widx < 2 * HID) {
                int half = widx >> 11;
                int r = widx & (HID - 1);
                int c0 = half * (FF / 2);
                float a0, a1;
                warp_dot2((const float4*)(W + (size_t)r * FF + c0),
                          (const float4*)(g_h1 + c0),
                          (const float4*)(g_h1 + FF + c0), FF / 8, lane, a0, a1);
                if (lane == 0) {
                    g_fp[(half * NB + 0) * HID + r] = a0;
                    g_fp[(half * NB + 1) * HID + r] = a1;
                }
            }
        }
        gbar();

        // ---------- FFN2 combine, residual add ----------
        {
            int idx = bid * NTHR + tid;
            if (idx < NB * HID) {
                int b = idx >> 11;
                int r = idx & (HID - 1);
                g_x[b * HID + r] += g_fp[b * HID + r] + g_fp[(NB + b) * HID + r];
            }
        }
        gbar();
    }

    // ---------- LN + logits gemv ----------
    {
        do_ln(ln_g, ln_b, s_xn, s_red);
        for (int r = widx; r < NV; r += TOTW) {
            float a0, a1;
            warp_dot2((const float4*)(out_w + (size_t)r * HID), (const float4*)s_xn,
                      (const float4*)(s_xn + HID), HID / 4, lane, a0, a1);
            if (lane == 0) {
                g_logits[r] = a0;
                g_logits[NV + r] = a1;
            }
        }
    }
    gbar();

    // ---------- softmax phase A: per-block slice partials ----------
    {
        int start = bid * VSLICE;
        int cnt = min(VSLICE, NV - start);
        if (cnt < 0) cnt = 0;
#pragma unroll
        for (int b = 0; b < NB; b++) {
            const float* lg = g_logits + b * NV + start;
            float m = -1e30f;
            for (int i = tid; i < cnt; i += NTHR) m = fmaxf(m, lg[i]);
            m = blk_max(m, s_red);
            float s = 0.f;
            for (int i = tid; i < cnt; i += NTHR) s += expf(lg[i] - m);
            s = blk_sum(s, s_red);
            if (tid == 0) {
                g_sm[(b * NBLK + bid) * 2]     = m;
                g_sm[(b * NBLK + bid) * 2 + 1] = s;
            }
        }
    }
    gbar();

    // ---------- softmax phase B: global combine + write output ----------
    {
        if (tid < NB * NBLK * 2) s_xn[tid] = g_sm[tid];
        __syncthreads();
        int start = bid * VSLICE;
        int cnt = min(VSLICE, NV - start);
        if (cnt < 0) cnt = 0;
#pragma unroll
        for (int b = 0; b < NB; b++) {
            float M = -1e30f;
            for (int k = 0; k < NBLK; k++) M = fmaxf(M, s_xn[(b * NBLK + k) * 2]);
            float S = 0.f;
            for (int k = 0; k < NBLK; k++)
                S += s_xn[(b * NBLK + k) * 2 + 1] * expf(s_xn[(b * NBLK + k) * 2] - M);
            float invS = 1.f / S;
            const float* lg = g_logits + b * NV + start;
            float* op = out + b * NV + start;
            for (int i = tid; i < cnt; i += NTHR) op[i] = expf(lg[i] - M) * invS;
        }
    }
}

extern "C" void kernel_launch(void* const* d_in, const int* in_sizes, int n_in,
                              void* d_out, int out_size) {
    const float* x      = (const float*)d_in[0];
    const float* qkv_w  = (const float*)d_in[1];
    const float* ffn1_w = (const float*)d_in[2];
    const float* ffn2_w = (const float*)d_in[3];
    const float* out_w  = (const float*)d_in[4];
    const float* ln_g   = (const float*)d_in[5];
    const float* ln_b   = (const float*)d_in[6];
    float* kheap        = (float*)d_in[7];
    float* vheap        = (float*)d_in[8];
    const float* koff   = (const float*)d_in[9];
    const float* voff   = (const float*)d_in[10];
    (void)in_sizes; (void)n_in; (void)out_size;

    mega_kernel<<<NBLK, NTHR>>>(x, qkv_w, ffn1_w, ffn2_w, out_w, ln_g, ln_b,
                                kheap, vheap, koff, voff, (float*)d_out);
}